// round 6
// baseline (speedup 1.0000x reference)
#include <cuda_runtime.h>
#include <stdint.h>

#define Bv  2
#define Nv  2048
#define Dv  1024
#define Hv  16
#define DHv 64
#define Mv  (Bv*Nv)

// ---------------------------------------------------------------------------
// Scratch (device globals). Packed arrays store (hi,lo) float2 per element.
// ---------------------------------------------------------------------------
__device__ float g_Xp[(size_t)3 * Mv * Dv * 2];   // packed inputs q,k,v
__device__ float g_Wp[(size_t)4 * Dv * Dv * 2];   // packed Wq,Wk,Wv,Wo
__device__ float g_Qr[(size_t)Mv * Dv];           // Q projection (raw fp32)
__device__ float g_Kp[(size_t)Mv * Dv * 2];       // K projection packed
__device__ float g_Vp[(size_t)Mv * Dv * 2];       // V projection packed
__device__ float g_Ap[(size_t)Mv * Dv * 2];       // attention out packed

// ---------------------------------------------------------------------------
// helpers
// ---------------------------------------------------------------------------
__device__ __forceinline__ uint32_t f2tf(float f) {
    uint32_t r;
    asm("cvt.rna.tf32.f32 %0, %1;" : "=r"(r) : "f"(f));
    return r;
}
__device__ __forceinline__ void tfsplit(float x, uint32_t& hi, uint32_t& lo) {
    hi = f2tf(x);
    lo = f2tf(x - __uint_as_float(hi));
}
__device__ __forceinline__ uint32_t f2u(float f) { return __float_as_uint(f); }
__device__ __forceinline__ float u2f(uint32_t u) { return __uint_as_float(u); }

#define MMA_TF32(d, a0, a1, a2, a3, b0, b1)                                   \
    asm volatile(                                                             \
        "mma.sync.aligned.m16n8k8.row.col.f32.tf32.tf32.f32 "                 \
        "{%0,%1,%2,%3},{%4,%5,%6,%7},{%8,%9},{%0,%1,%2,%3};"                  \
        : "+f"(d[0]), "+f"(d[1]), "+f"(d[2]), "+f"(d[3])                      \
        : "r"(a0), "r"(a1), "r"(a2), "r"(a3), "r"(b0), "r"(b1))

#define MMA3(d, ah, al, bh, bl)                                               \
    MMA_TF32(d, ah[0], ah[1], ah[2], ah[3], bh[0], bh[1]);                    \
    MMA_TF32(d, ah[0], ah[1], ah[2], ah[3], bl[0], bl[1]);                    \
    MMA_TF32(d, al[0], al[1], al[2], al[3], bh[0], bh[1]);

__device__ __forceinline__ void cp_async16(uint32_t daddr, const void* src) {
    asm volatile("cp.async.cg.shared.global [%0], [%1], 16;"
                 :: "r"(daddr), "l"(src));
}

__device__ __forceinline__ float4 split2pack(float2 v) {
    uint32_t h0, l0, h1, l1;
    tfsplit(v.x, h0, l0);
    tfsplit(v.y, h1, l1);
    return make_float4(u2f(h0), u2f(l0), u2f(h1), u2f(l1));
}

// ---------------------------------------------------------------------------
// prepass: split into packed (hi,lo) float2-per-element arrays
// ---------------------------------------------------------------------------
__global__ __launch_bounds__(256) void split3_kernel(
    const float* __restrict__ a, const float* __restrict__ b,
    const float* __restrict__ c, float* __restrict__ dst)
{
    const float* src = (blockIdx.y == 0) ? a : (blockIdx.y == 1) ? b : c;
    size_t off = (size_t)blockIdx.y * Mv * Dv;
    size_t i = ((size_t)blockIdx.x * 256 + threadIdx.x) * 2;
    *(float4*)(dst + 2 * (off + i)) = split2pack(*(const float2*)(src + i));
}

__global__ __launch_bounds__(256) void splitW_kernel(
    const float* __restrict__ w0, const float* __restrict__ w1,
    const float* __restrict__ w2, const float* __restrict__ w3,
    float* __restrict__ dst)
{
    const float* src = (blockIdx.y == 0) ? w0 : (blockIdx.y == 1) ? w1
                     : (blockIdx.y == 2) ? w2 : w3;
    size_t off = (size_t)blockIdx.y * Dv * Dv;
    size_t i = ((size_t)blockIdx.x * 256 + threadIdx.x) * 2;
    *(float4*)(dst + 2 * (off + i)) = split2pack(*(const float2*)(src + i));
}

// ---------------------------------------------------------------------------
// GEMM body: Y[m,n] = sum_k X[m,k]*W[n,k] + bias[n], packed operands.
// CTA 128x128, Kc=16, split-tf32 (3 MMAs), cp.async double buffer.
// smem stride 20 float2 (20 mod 16 == 4 -> <=2 hits per bank pair on LDS.64).
// ---------------------------------------------------------------------------
#define GK   16
#define GS2  20
#define GT2  (128 * GS2)          // float2 per tile buffer
#define GSMEM (4 * GT2 * 8)       // A[2]+B[2] buffers in bytes

__device__ __forceinline__ void gemm_body(
    const float* __restrict__ Xp, const float* __restrict__ Wp,
    const float* __restrict__ bias,
    float* __restrict__ Yr, float* __restrict__ Yp,
    int m0, int n0)
{
    extern __shared__ float smf[];
    float2* As2 = (float2*)smf;        // [2][128][20]
    float2* Bs2 = As2 + 2 * GT2;       // [2][128][20]

    const int t    = threadIdx.x;
    const int lane = t & 31;
    const int warp = t >> 5;
    const int gid  = lane >> 2;
    const int tq   = lane & 3;
    const int wm   = warp >> 2;   // 0..1
    const int wn   = warp & 3;    // 0..3

    const uint32_t sbase = (uint32_t)__cvta_generic_to_shared(smf);

    float acc[4][4][4];
#pragma unroll
    for (int mf = 0; mf < 4; mf++)
#pragma unroll
        for (int nf = 0; nf < 4; nf++)
#pragma unroll
            for (int c = 0; c < 4; c++) acc[mf][nf][c] = 0.0f;

    // one K-chunk: per operand 128 rows x 8 chunks(16B = 2 elements)
#define GEMM_ISSUE(buf, k0)                                                    \
    {                                                                          \
        _Pragma("unroll")                                                      \
        for (int i = 0; i < 4; i++) {                                          \
            int idx = t + i * 256;                                             \
            int row = idx >> 3;                                                \
            int ce  = (idx & 7) * 2;                                           \
            uint32_t so = ((buf) * GT2 + row * GS2 + ce) * 8;                  \
            cp_async16(sbase + so,                                             \
                       Xp + 2 * ((size_t)(m0 + row) * Dv + (k0) + ce));        \
            cp_async16(sbase + 2 * GT2 * 8 + so,                               \
                       Wp + 2 * ((size_t)(n0 + row) * Dv + (k0) + ce));        \
        }                                                                      \
        asm volatile("cp.async.commit_group;");                                \
    }

    GEMM_ISSUE(0, 0);

    for (int it = 0; it < Dv / GK; it++) {
        asm volatile("cp.async.wait_group 0;" ::: "memory");
        __syncthreads();
        if (it + 1 < Dv / GK) GEMM_ISSUE((it + 1) & 1, (it + 1) * GK);

        const float2* A = As2 + (it & 1) * GT2;
        const float2* B = Bs2 + (it & 1) * GT2;

#pragma unroll
        for (int ks = 0; ks < 2; ks++) {
            const int c = ks * 8 + tq;
            uint32_t ah[4][4], al[4][4];
#pragma unroll
            for (int mf = 0; mf < 4; mf++) {
                int r = wm * 64 + mf * 16 + gid;
                float2 a0 = A[r * GS2 + c];
                float2 a1 = A[(r + 8) * GS2 + c];
                float2 a2 = A[r * GS2 + c + 4];
                float2 a3 = A[(r + 8) * GS2 + c + 4];
                ah[mf][0] = f2u(a0.x); al[mf][0] = f2u(a0.y);
                ah[mf][1] = f2u(a1.x); al[mf][1] = f2u(a1.y);
                ah[mf][2] = f2u(a2.x); al[mf][2] = f2u(a2.y);
                ah[mf][3] = f2u(a3.x); al[mf][3] = f2u(a3.y);
            }
#pragma unroll
            for (int nf = 0; nf < 4; nf++) {
                int n = wn * 32 + nf * 8 + gid;
                float2 b0 = B[n * GS2 + c];
                float2 b1 = B[n * GS2 + c + 4];
                uint32_t bh[2], bl[2];
                bh[0] = f2u(b0.x); bl[0] = f2u(b0.y);
                bh[1] = f2u(b1.x); bl[1] = f2u(b1.y);
#pragma unroll
                for (int mf = 0; mf < 4; mf++) {
                    MMA3(acc[mf][nf], ah[mf], al[mf], bh, bl);
                }
            }
        }
    }

    // epilogue
#pragma unroll
    for (int nf = 0; nf < 4; nf++) {
        int col = n0 + wn * 32 + nf * 8 + tq * 2;
        float2 bb = *(const float2*)&bias[col];
#pragma unroll
        for (int mf = 0; mf < 4; mf++) {
            int r = m0 + wm * 64 + mf * 16 + gid;
            float v0 = acc[mf][nf][0] + bb.x;
            float v1 = acc[mf][nf][1] + bb.y;
            float v2 = acc[mf][nf][2] + bb.x;
            float v3 = acc[mf][nf][3] + bb.y;
            if (Yr) {
                *(float2*)&Yr[(size_t)r * Dv + col]       = make_float2(v0, v1);
                *(float2*)&Yr[(size_t)(r + 8) * Dv + col] = make_float2(v2, v3);
            } else {
                *(float4*)&Yp[2 * ((size_t)r * Dv + col)] =
                    split2pack(make_float2(v0, v1));
                *(float4*)&Yp[2 * ((size_t)(r + 8) * Dv + col)] =
                    split2pack(make_float2(v2, v3));
            }
        }
    }
}

// fused QKV projection: grid.z selects q/k/v
__global__ __launch_bounds__(256, 2) void gemm_qkv(
    const float* __restrict__ Xp, const float* __restrict__ Wp,
    const float* __restrict__ bq, const float* __restrict__ bk,
    const float* __restrict__ bv,
    float* __restrict__ Qr, float* __restrict__ Kp, float* __restrict__ Vp)
{
    const int z = blockIdx.z;
    const float* xp = Xp + (size_t)z * Mv * Dv * 2;
    const float* wp = Wp + (size_t)z * Dv * Dv * 2;
    const float* bias = (z == 0) ? bq : (z == 1) ? bk : bv;
    float* yr = (z == 0) ? Qr : nullptr;
    float* yp = (z == 1) ? Kp : Vp;
    gemm_body(xp, wp, bias, yr, yp, blockIdx.y * 128, blockIdx.x * 128);
}

__global__ __launch_bounds__(256, 2) void gemm_out(
    const float* __restrict__ Xp, const float* __restrict__ Wp,
    const float* __restrict__ bias, float* __restrict__ Yr)
{
    gemm_body(Xp, Wp, bias, Yr, nullptr, blockIdx.y * 128, blockIdx.x * 128);
}

// ---------------------------------------------------------------------------
// Flash attention, split-tf32, packed (hi,lo) K/V from gmem, Q split in regs,
// P packed in smem, cross-phase cp.async pipelining (K(kt+1) after S-barrier,
// V(kt+1) after PV-barrier).
// smem stride 68 float2 (68 mod 16 == 4).
// ---------------------------------------------------------------------------
#define AS2 68
#define AT2 (64 * AS2)                 // float2 per tile
#define NT  (Nv / 64)
#define ASMEM (3 * AT2 * 8 + (64 + 64 + 128 + 128) * 4)

__global__ __launch_bounds__(256, 2) void attn_tc(
    const float* __restrict__ Qr,
    const float* __restrict__ Kp, const float* __restrict__ Vp,
    float* __restrict__ Ap)
{
    extern __shared__ float smf[];
    float2* Ks2 = (float2*)smf;        // [64][68] packed K
    float2* Ps2 = Ks2 + AT2;           // [64][68] packed P (raw Q staging 1st)
    float2* Vs2 = Ps2 + AT2;           // [64][68] packed V
    float* mstate = (float*)(Vs2 + AT2);   // [64]
    float* lstate = mstate + 64;           // [64]
    float* pmax   = lstate + 64;           // [2][64]
    float* psum   = pmax + 128;            // [2][64]

    const int t    = threadIdx.x;
    const int lane = t & 31;
    const int warp = t >> 5;
    const int gid  = lane >> 2;
    const int tq   = lane & 3;
    const int wm   = warp >> 1;   // 0..3
    const int wn   = warp & 1;    // 0..1
    const int q0   = blockIdx.x * 64;
    const size_t base =
        (size_t)blockIdx.z * Nv * Dv + (size_t)blockIdx.y * DHv;

    const uint32_t sb  = (uint32_t)__cvta_generic_to_shared(smf);
    const uint32_t sbK = sb;
    const uint32_t sbV = sb + 2 * AT2 * 8;

    // tile row = 64 elements = 128 floats = 512B = 32 chunks; 2048 chunks/tile
#define ISSUE_K(kt)                                                            \
    {                                                                          \
        _Pragma("unroll")                                                      \
        for (int i = 0; i < 8; i++) {                                          \
            int idx = t + i * 256;                                             \
            int row = idx >> 5;                                                \
            int ce  = (idx & 31) * 2;                                          \
            cp_async16(sbK + (row * AS2 + ce) * 8,                             \
                Kp + 2 * (base + (size_t)((kt) * 64 + row) * Dv + ce));        \
        }                                                                      \
        asm volatile("cp.async.commit_group;");                                \
    }
#define ISSUE_V(kt)                                                            \
    {                                                                          \
        _Pragma("unroll")                                                      \
        for (int i = 0; i < 8; i++) {                                          \
            int idx = t + i * 256;                                             \
            int row = idx >> 5;                                                \
            int ce  = (idx & 31) * 2;                                          \
            cp_async16(sbV + (row * AS2 + ce) * 8,                             \
                Vp + 2 * (base + (size_t)((kt) * 64 + row) * Dv + ce));        \
        }                                                                      \
        asm volatile("cp.async.commit_group;");                                \
    }

    ISSUE_K(0);
    ISSUE_V(0);

    // stage raw Q into Ps region (float layout, stride 68 floats)
    float* Qstage = (float*)Ps2;
#pragma unroll
    for (int i = 0; i < 4; i++) {
        int idx = t + i * 256;
        int r   = idx >> 4;
        int c4  = (idx & 15) << 2;
        float4 v = *(const float4*)&Qr[base + (size_t)(q0 + r) * Dv + c4];
        Qstage[r * 68 + c4 + 0] = v.x;
        Qstage[r * 68 + c4 + 1] = v.y;
        Qstage[r * 68 + c4 + 2] = v.z;
        Qstage[r * 68 + c4 + 3] = v.w;
    }
    if (t < 64) { mstate[t] = -1e30f; lstate[t] = 0.0f; }
    __syncthreads();

    // Q fragments -> split once into registers
    uint32_t qh[8][4], ql[8][4];
    {
        const int r = wm * 16 + gid;
#pragma unroll
        for (int ks = 0; ks < 8; ks++) {
            int c = ks * 8 + tq;
            tfsplit(Qstage[r * 68 + c],           qh[ks][0], ql[ks][0]);
            tfsplit(Qstage[(r + 8) * 68 + c],     qh[ks][1], ql[ks][1]);
            tfsplit(Qstage[r * 68 + c + 4],       qh[ks][2], ql[ks][2]);
            tfsplit(Qstage[(r + 8) * 68 + c + 4], qh[ks][3], ql[ks][3]);
        }
    }
    __syncthreads();   // Q staging reads done before P writes reuse region

    float o[4][4];
#pragma unroll
    for (int nf = 0; nf < 4; nf++)
#pragma unroll
        for (int c = 0; c < 4; c++) o[nf][c] = 0.0f;

    const int r_lo = wm * 16 + gid;
    const int r_hi = r_lo + 8;

    for (int kt = 0; kt < NT; kt++) {
        // K(kt) complete (V(kt) may still be in flight)
        asm volatile("cp.async.wait_group 1;" ::: "memory");
        __syncthreads();

        // S = Q K^T
        float s[4][4];
#pragma unroll
        for (int nf = 0; nf < 4; nf++)
#pragma unroll
            for (int c = 0; c < 4; c++) s[nf][c] = 0.0f;
#pragma unroll
        for (int ks = 0; ks < 8; ks++) {
            const int c = ks * 8 + tq;
#pragma unroll
            for (int nf = 0; nf < 4; nf++) {
                int n = wn * 32 + nf * 8 + gid;
                float2 b0 = Ks2[n * AS2 + c];
                float2 b1 = Ks2[n * AS2 + c + 4];
                uint32_t bh[2], bl[2];
                bh[0] = f2u(b0.x); bl[0] = f2u(b0.y);
                bh[1] = f2u(b1.x); bl[1] = f2u(b1.y);
                MMA3(s[nf], qh[ks], ql[ks], bh, bl);
            }
        }

        // phase A: per-row max
        float mx_lo = -1e30f, mx_hi = -1e30f;
#pragma unroll
        for (int nf = 0; nf < 4; nf++) {
            mx_lo = fmaxf(mx_lo, fmaxf(s[nf][0], s[nf][1]));
            mx_hi = fmaxf(mx_hi, fmaxf(s[nf][2], s[nf][3]));
        }
        mx_lo = fmaxf(mx_lo, __shfl_xor_sync(0xffffffffu, mx_lo, 1));
        mx_lo = fmaxf(mx_lo, __shfl_xor_sync(0xffffffffu, mx_lo, 2));
        mx_hi = fmaxf(mx_hi, __shfl_xor_sync(0xffffffffu, mx_hi, 1));
        mx_hi = fmaxf(mx_hi, __shfl_xor_sync(0xffffffffu, mx_hi, 2));
        if (tq == 0) {
            pmax[wn * 64 + r_lo] = mx_lo;
            pmax[wn * 64 + r_hi] = mx_hi;
        }
        __syncthreads();   // all warps done reading Ks

        if (kt + 1 < NT) ISSUE_K(kt + 1);

        // phase B: exp, sums, stage packed P, rescale O
        float m_old_lo = mstate[r_lo], m_old_hi = mstate[r_hi];
        float nm_lo = fmaxf(m_old_lo, fmaxf(pmax[r_lo], pmax[64 + r_lo]));
        float nm_hi = fmaxf(m_old_hi, fmaxf(pmax[r_hi], pmax[64 + r_hi]));
        float sc_lo = __expf(m_old_lo - nm_lo);
        float sc_hi = __expf(m_old_hi - nm_hi);
        float sum_lo = 0.0f, sum_hi = 0.0f;
#pragma unroll
        for (int nf = 0; nf < 4; nf++) {
            float p0 = __expf(s[nf][0] - nm_lo);
            float p1 = __expf(s[nf][1] - nm_lo);
            float p2 = __expf(s[nf][2] - nm_hi);
            float p3 = __expf(s[nf][3] - nm_hi);
            sum_lo += p0 + p1;
            sum_hi += p2 + p3;
            int col = wn * 32 + nf * 8 + tq * 2;
            *(float4*)&Ps2[r_lo * AS2 + col] = split2pack(make_float2(p0, p1));
            *(float4*)&Ps2[r_hi * AS2 + col] = split2pack(make_float2(p2, p3));
        }
        sum_lo += __shfl_xor_sync(0xffffffffu, sum_lo, 1);
        sum_lo += __shfl_xor_sync(0xffffffffu, sum_lo, 2);
        sum_hi += __shfl_xor_sync(0xffffffffu, sum_hi, 1);
        sum_hi += __shfl_xor_sync(0xffffffffu, sum_hi, 2);
        if (tq == 0) {
            psum[wn * 64 + r_lo] = sum_lo;
            psum[wn * 64 + r_hi] = sum_hi;
        }
#pragma unroll
        for (int nf = 0; nf < 4; nf++) {
            o[nf][0] *= sc_lo; o[nf][1] *= sc_lo;
            o[nf][2] *= sc_hi; o[nf][3] *= sc_hi;
        }

        // V(kt) complete; outstanding after this: K(kt+1) (if any)
        if (kt + 1 < NT) {
            asm volatile("cp.async.wait_group 1;" ::: "memory");
        } else {
            asm volatile("cp.async.wait_group 0;" ::: "memory");
        }
        __syncthreads();   // P + psum + Vs visible

        if (wn == 0 && tq == 0) {
            lstate[r_lo] = lstate[r_lo] * sc_lo + psum[r_lo] + psum[64 + r_lo];
            lstate[r_hi] = lstate[r_hi] * sc_hi + psum[r_hi] + psum[64 + r_hi];
            mstate[r_lo] = nm_lo;
            mstate[r_hi] = nm_hi;
        }

        // O += P V
#pragma unroll
        for (int ks = 0; ks < 8; ks++) {
            const int c = ks * 8 + tq;
            float2 p0 = Ps2[r_lo * AS2 + c];
            float2 p1 = Ps2[r_hi * AS2 + c];
            float2 p2 = Ps2[r_lo * AS2 + c + 4];
            float2 p3 = Ps2[r_hi * AS2 + c + 4];
            uint32_t ph[4], pl[4];
            ph[0] = f2u(p0.x); pl[0] = f2u(p0.y);
            ph[1] = f2u(p1.x); pl[1] = f2u(p1.y);
            ph[2] = f2u(p2.x); pl[2] = f2u(p2.y);
            ph[3] = f2u(p3.x); pl[3] = f2u(p3.y);
#pragma unroll
            for (int nf = 0; nf < 4; nf++) {
                int n = wn * 32 + nf * 8 + gid;
                float2 v0 = Vs2[(ks * 8 + tq) * AS2 + n];
                float2 v1 = Vs2[(ks * 8 + tq + 4) * AS2 + n];
                uint32_t bh[2], bl[2];
                bh[0] = f2u(v0.x); bl[0] = f2u(v0.y);
                bh[1] = f2u(v1.x); bl[1] = f2u(v1.y);
                MMA3(o[nf], ph, pl, bh, bl);
            }
        }

        __syncthreads();   // all warps done reading Vs
        if (kt + 1 < NT) ISSUE_V(kt + 1);
    }

    float inv_lo = 1.0f / lstate[r_lo];
    float inv_hi = 1.0f / lstate[r_hi];
#pragma unroll
    for (int nf = 0; nf < 4; nf++) {
        int col = wn * 32 + nf * 8 + tq * 2;
        float v0 = o[nf][0] * inv_lo, v1 = o[nf][1] * inv_lo;
        *(float4*)&Ap[2 * (base + (size_t)(q0 + r_lo) * Dv + col)] =
            split2pack(make_float2(v0, v1));
        float v2 = o[nf][2] * inv_hi, v3 = o[nf][3] * inv_hi;
        *(float4*)&Ap[2 * (base + (size_t)(q0 + r_hi) * Dv + col)] =
            split2pack(make_float2(v2, v3));
    }
}

// ---------------------------------------------------------------------------
extern "C" void kernel_launch(void* const* d_in, const int* in_sizes, int n_in,
                              void* d_out, int out_size)
{
    const float* q  = (const float*)d_in[0];
    const float* k  = (const float*)d_in[1];
    const float* v  = (const float*)d_in[2];
    const float* Wq = (const float*)d_in[3];
    const float* bq = (const float*)d_in[4];
    const float* Wk = (const float*)d_in[5];
    const float* bk = (const float*)d_in[6];
    const float* Wv = (const float*)d_in[7];
    const float* bv = (const float*)d_in[8];
    const float* Wo = (const float*)d_in[9];
    const float* bo = (const float*)d_in[10];
    float* out = (float*)d_out;

    float *xp, *wp, *qr, *kp, *vp, *ap;
    cudaGetSymbolAddress((void**)&xp, g_Xp);
    cudaGetSymbolAddress((void**)&wp, g_Wp);
    cudaGetSymbolAddress((void**)&qr, g_Qr);
    cudaGetSymbolAddress((void**)&kp, g_Kp);
    cudaGetSymbolAddress((void**)&vp, g_Vp);
    cudaGetSymbolAddress((void**)&ap, g_Ap);

    cudaFuncSetAttribute(gemm_qkv,
                         cudaFuncAttributeMaxDynamicSharedMemorySize, GSMEM);
    cudaFuncSetAttribute(gemm_out,
                         cudaFuncAttributeMaxDynamicSharedMemorySize, GSMEM);
    cudaFuncSetAttribute(attn_tc,
                         cudaFuncAttributeMaxDynamicSharedMemorySize, ASMEM);

    split3_kernel<<<dim3(Mv * Dv / 512, 3), 256>>>(q, k, v, xp);
    splitW_kernel<<<dim3(Dv * Dv / 512, 4), 256>>>(Wq, Wk, Wv, Wo, wp);

    dim3 gg(Dv / 128, Mv / 128, 3);  // (8, 32, 3) fused QKV
    gemm_qkv<<<gg, 256, GSMEM>>>(xp, wp, bq, bk, bv, qr, kp, vp);

    attn_tc<<<dim3(Nv / 64, Hv, Bv), 256, ASMEM>>>(qr, kp, vp, ap);

    gemm_out<<<dim3(Dv / 128, Mv / 128), 256, GSMEM>>>(
        ap, wp + 3 * (size_t)Dv * Dv * 2, bo, out);
}